// round 10
// baseline (speedup 1.0000x reference)
#include <cuda_runtime.h>
#include <math.h>

#define T_   1024
#define B_   32
#define IN_  1024
#define H_   512
#define TB_  (T_ * B_)

typedef unsigned long long ull;

// ---------------- static device scratch (no runtime alloc allowed) ----------
__device__ float g_xin[2][(size_t)TB_ * H_];   // per-direction input projections (biases folded)
__device__ float g_seq[(size_t)TB_ * 2 * H_];  // layer-0 output, [t][b][2H]

// ---------------- f32x2 helpers (ptxas never emits FFMA2 from C++) ----------
__device__ __forceinline__ ull pk2(float lo, float hi) {
    ull r; asm("mov.b64 %0, {%1,%2};" : "=l"(r) : "f"(lo), "f"(hi)); return r;
}
__device__ __forceinline__ void upk2(ull v, float& lo, float& hi) {
    asm("mov.b64 {%0,%1}, %2;" : "=f"(lo), "=f"(hi) : "l"(v));
}
__device__ __forceinline__ void fma2(ull& d, ull a, ull b) {
    asm("fma.rn.f32x2 %0, %1, %2, %0;" : "+l"(d) : "l"(a), "l"(b));
}
__device__ __forceinline__ unsigned smem_u32(const void* p) {
    unsigned a;
    asm("{ .reg .u64 t; cvta.to.shared.u64 t, %1; cvt.u32.u64 %0, t; }" : "=r"(a) : "l"(p));
    return a;
}
// DSMEM 16B push to peer rank (relaxed; ordered by same-thread release below)
__device__ __forceinline__ void dsmem_st_v4(unsigned laddr, unsigned rank, float4 q) {
    asm volatile(
        "{\n\t.reg .u32 ra;\n\t"
        "mapa.shared::cluster.u32 ra, %0, %1;\n\t"
        "st.shared::cluster.v4.f32 [ra], {%2,%3,%4,%5};\n\t}"
        :: "r"(laddr), "r"(rank), "f"(q.x), "f"(q.y), "f"(q.z), "f"(q.w) : "memory");
}
// Release-store of a flag word on peer rank (orders THIS thread's prior pushes)
__device__ __forceinline__ void dsmem_release_flag(unsigned laddr, unsigned rank, unsigned val) {
    asm volatile(
        "{\n\t.reg .u32 ra;\n\t"
        "mapa.shared::cluster.u32 ra, %0, %1;\n\t"
        "st.release.cluster.shared::cluster.u32 [ra], %2;\n\t}"
        :: "r"(laddr), "r"(rank), "r"(val) : "memory");
}
// Acquire-poll local flag until >= tgt
__device__ __forceinline__ void poll_ge(unsigned laddr, unsigned tgt) {
    unsigned v;
    do {
        asm volatile("ld.acquire.cluster.shared::cta.u32 %0, [%1];"
                     : "=r"(v) : "r"(laddr) : "memory");
    } while (v < tgt);
}

// ---------------------------------------------------------------------------
// Input-projection GEMM (register-prefetch pipelined) — unchanged.
// ---------------------------------------------------------------------------
__global__ __launch_bounds__(256, 2) void gemm_kernel(
    const float* __restrict__ x,
    const float* __restrict__ w_ih,
    const float* __restrict__ b_ih,
    const float* __restrict__ b_hh,
    const float* __restrict__ noise_in,
    int layer)
{
    __shared__ float As[16 * 132];   // [k][m], padded
    __shared__ float Bs[16 * 68];    // [k][n], padded

    const int tid  = threadIdx.x;
    const int cell = blockIdx.z;
    const int cabs = layer * 2 + cell;
    const int n0   = blockIdx.x * 64;
    const int m0   = blockIdx.y * 128;
    const int tx   = tid & 15;
    const int ty   = tid >> 4;
    const int msub = ty * 8;
    const int nsub = tx * 4;

    const float* A  = (layer == 0) ? x : g_seq;
    const float* nz = noise_in + (size_t)cabs * B_ * IN_;
    const float* wb = w_ih + (size_t)cabs * H_ * IN_;
    float* outp = g_xin[cell];

    ull acc[4][4];
#pragma unroll
    for (int i = 0; i < 4; i++)
#pragma unroll
        for (int j = 0; j < 4; j++) acc[i][j] = 0ull;

    const int e0 = tid, e1 = tid + 256;
    const int row0 = e0 >> 2, kq0 = (e0 & 3) * 4;
    const int row1 = e1 >> 2, kq1 = (e1 & 3) * 4;
    size_t ab0, ab1;
    if (layer == 0) {   // m = t*B + b ; x addr = b*(T*IN) + t*IN
        ab0 = (size_t)(row0 & 31) * ((size_t)T_ * IN_) + (size_t)(m0 / 32 + (row0 >> 5)) * IN_;
        ab1 = (size_t)(row1 & 31) * ((size_t)T_ * IN_) + (size_t)(m0 / 32 + (row1 >> 5)) * IN_;
    } else {
        ab0 = (size_t)(m0 + row0) * IN_;
        ab1 = (size_t)(m0 + row1) * IN_;
    }
    const size_t nb0 = (size_t)(row0 & 31) * IN_;
    const size_t nb1 = (size_t)(row1 & 31) * IN_;
    const int brow = tid >> 2, bkq = (tid & 3) * 4;
    const float* wrow = wb + (size_t)(n0 + brow) * IN_ + bkq;

    float4 xv0 = *(const float4*)(A + ab0 + kq0);
    float4 nv0 = *(const float4*)(nz + nb0 + kq0);
    float4 xv1 = *(const float4*)(A + ab1 + kq1);
    float4 nv1 = *(const float4*)(nz + nb1 + kq1);
    float4 wv0 = *(const float4*)(wrow);

    for (int k0 = 0; k0 < IN_; k0 += 16) {
        As[(kq0 + 0) * 132 + row0] = xv0.x * nv0.x;
        As[(kq0 + 1) * 132 + row0] = xv0.y * nv0.y;
        As[(kq0 + 2) * 132 + row0] = xv0.z * nv0.z;
        As[(kq0 + 3) * 132 + row0] = xv0.w * nv0.w;
        As[(kq1 + 0) * 132 + row1] = xv1.x * nv1.x;
        As[(kq1 + 1) * 132 + row1] = xv1.y * nv1.y;
        As[(kq1 + 2) * 132 + row1] = xv1.z * nv1.z;
        As[(kq1 + 3) * 132 + row1] = xv1.w * nv1.w;
        Bs[(bkq + 0) * 68 + brow] = wv0.x;
        Bs[(bkq + 1) * 68 + brow] = wv0.y;
        Bs[(bkq + 2) * 68 + brow] = wv0.z;
        Bs[(bkq + 3) * 68 + brow] = wv0.w;
        __syncthreads();

        const int kn = k0 + 16;
        if (kn < IN_) {
            xv0 = *(const float4*)(A + ab0 + kn + kq0);
            nv0 = *(const float4*)(nz + nb0 + kn + kq0);
            xv1 = *(const float4*)(A + ab1 + kn + kq1);
            nv1 = *(const float4*)(nz + nb1 + kn + kq1);
            wv0 = *(const float4*)(wrow + kn);
        }

#pragma unroll
        for (int k = 0; k < 16; k++) {
            float4 b4 = *(const float4*)&Bs[k * 68 + nsub];
            ull bd0 = pk2(b4.x, b4.x);
            ull bd1 = pk2(b4.y, b4.y);
            ull bd2 = pk2(b4.z, b4.z);
            ull bd3 = pk2(b4.w, b4.w);
#pragma unroll
            for (int mp = 0; mp < 4; mp++) {
                ull au = *(const ull*)&As[k * 132 + msub + 2 * mp];
                fma2(acc[mp][0], au, bd0);
                fma2(acc[mp][1], au, bd1);
                fma2(acc[mp][2], au, bd2);
                fma2(acc[mp][3], au, bd3);
            }
        }
        __syncthreads();
    }

    float bi[4];
#pragma unroll
    for (int nn = 0; nn < 4; nn++) {
        int n = n0 + nsub + nn;
        bi[nn] = b_ih[cabs * H_ + n] + b_hh[cabs * H_ + n];
    }
#pragma unroll
    for (int mp = 0; mp < 4; mp++) {
        float lo[4], hi[4];
#pragma unroll
        for (int nn = 0; nn < 4; nn++) upk2(acc[mp][nn], lo[nn], hi[nn]);
        float4 v0 = make_float4(lo[0] + bi[0], lo[1] + bi[1], lo[2] + bi[2], lo[3] + bi[3]);
        float4 v1 = make_float4(hi[0] + bi[0], hi[1] + bi[1], hi[2] + bi[2], hi[3] + bi[3]);
        size_t r0 = (size_t)(m0 + msub + 2 * mp) * H_ + n0 + nsub;
        *(float4*)(outp + r0)      = v0;
        *(float4*)(outp + r0 + H_) = v1;
    }
}

// ---------------------------------------------------------------------------
// Recurrent scan v4: point-to-point dataflow, NO per-step rendezvous.
// 16 clusters of 8 CTAs. CTA owns 4 batches x 64 h-cols, W_hh in registers.
// Producer warp w stages its 32 values (warp-sync), lanes 0-6 each push the
// block to ONE peer (8x st.shared::cluster.v4) then post a step-numbered flag
// with st.release.cluster (single-thread program-order release). Consumers
// acquire-poll the 8 per-warp flags of a slice right before consuming it.
// Double-buffered hbuf + monotonic flags => safe without any barrier.
// ---------------------------------------------------------------------------
__global__ __launch_bounds__(256, 1) __cluster_dims__(8, 1, 1)
void recur_kernel(
    const float* __restrict__ w_hh,
    const float* __restrict__ noise_h,
    const float* __restrict__ mask,
    float* __restrict__ out,      // d_out: [B,T,2H] (layer 1 writes here)
    float* __restrict__ hn,       // d_out + B*T*2H: [L*D,B,H]
    int layer)
{
    __shared__ float    hbuf[2][4 * 512];   // full h*nh vector, double buffered (16KB)
    __shared__ float    red2[4][4][64];     // [kp][b][hl] split-K partials (4KB)
    __shared__ float    stage[256];         // per-step production staging (1KB)
    __shared__ unsigned flags[2][64];       // [buf][src_rank*8 + warp] step flags

    const int tid  = threadIdx.x;
    const int bx   = blockIdx.x;
    const int dir  = bx >> 6;               // 0 fwd, 1 bwd
    const int rank = bx & 7;                // cluster rank == h-slice
    const int grp  = (bx >> 3) & 7;         // batch group
    const int b0   = grp * 4;
    const int h0   = rank * 64;
    const int kp   = tid >> 6;              // K partition AND owned batch b
    const int hl   = tid & 63;
    const int h    = h0 + hl;
    const int c    = layer * 2 + dir;
    const int w    = tid >> 5;              // warp id (0..7)
    const int lane = tid & 31;

    const unsigned hb_a = smem_u32(&hbuf[0][0]);
    const unsigned fl_a = smem_u32(&flags[0][0]);

    // zero flags, then cluster-wide sync before any peer can push
    if (tid < 128) ((unsigned*)flags)[tid] = 0u;
    __syncthreads();
    asm volatile("barrier.cluster.arrive.aligned;" ::: "memory");
    asm volatile("barrier.cluster.wait.aligned;"   ::: "memory");

    // W_hh slice into registers as aligned f32x2 pairs: w[h][kp*128 .. +127]
    union F4U2 { float4 f; ulonglong2 u; };
    ulonglong2 wu[32];
    {
        const float4* wp = (const float4*)(w_hh + ((size_t)c * H_ + h) * H_ + kp * 128);
#pragma unroll
        for (int i = 0; i < 32; i++) { F4U2 t; t.f = wp[i]; wu[i] = t.u; }
    }

    // per-thread recurrent state for output (b=kp, h)
    const float nh = noise_h[((size_t)c * B_ + b0 + kp) * H_ + h];
    float hprev = 0.0f;
    const float* xin = g_xin[dir];

    const int src0 = 2 * kp, src1 = 2 * kp + 1;   // the two slices this thread consumes
    // producer warp w's destination block (float offset in a buffer):
    const unsigned dblk = (unsigned)((w >> 1) * 512 + h0 + (w & 1) * 32);

    for (int t = 0; t < T_; t++) {
        const int ta = dir ? (T_ - 1 - t) : t;

        // prefetch xin + mask (long-latency, consumed in epilogue)
        const float xv = __ldg(xin + ((size_t)ta * B_ + b0 + kp) * H_ + h);
        const float mt = __ldg(mask + (size_t)(b0 + kp) * T_ + ta);

        ull acc[4] = {0ull, 0ull, 0ull, 0ull};
        if (t > 0) {
            const int buf = t & 1;
            const float4* hb = (const float4*)&hbuf[buf][0];
            const unsigned tgt = (unsigned)t;

            // slice src0 (K elems kp*128 .. +64) -> i = 0..15
            if (src0 != rank) {
                const unsigned fb = fl_a + (unsigned)(buf * 64 + src0 * 8) * 4u;
#pragma unroll
                for (int q = 0; q < 8; q++) poll_ge(fb + q * 4u, tgt);
            }
#pragma unroll
            for (int i = 0; i < 16; i++) {
                ulonglong2 w2 = wu[i];
#pragma unroll
                for (int b = 0; b < 4; b++) {
                    F4U2 q; q.f = hb[b * 128 + kp * 32 + i];
                    fma2(acc[b], q.u.x, w2.x);
                    fma2(acc[b], q.u.y, w2.y);
                }
            }
            // slice src1 (K elems kp*128+64 .. +128) -> i = 16..31
            if (src1 != rank) {
                const unsigned fb = fl_a + (unsigned)(buf * 64 + src1 * 8) * 4u;
#pragma unroll
                for (int q = 0; q < 8; q++) poll_ge(fb + q * 4u, tgt);
            }
#pragma unroll
            for (int i = 16; i < 32; i++) {
                ulonglong2 w2 = wu[i];
#pragma unroll
                for (int b = 0; b < 4; b++) {
                    F4U2 q; q.f = hb[b * 128 + kp * 32 + i];
                    fma2(acc[b], q.u.x, w2.x);
                    fma2(acc[b], q.u.y, w2.y);
                }
            }
        }
#pragma unroll
        for (int b = 0; b < 4; b++) {
            float lo, hi; upk2(acc[b], lo, hi);
            red2[kp][b][hl] = lo + hi;
        }
        __syncthreads();

        // epilogue: every thread finishes ONE output (b=kp, h)
        const float rec = red2[0][kp][hl] + red2[1][kp][hl]
                        + red2[2][kp][hl] + red2[3][kp][hl];
        const float hnew = tanhf(xv + rec);               // biases folded in xin
        const float hcur = hnew * mt + hprev * (1.0f - mt);
        hprev = hcur;
        const float v = hcur * nh;
        const int nb = (t + 1) & 1;
        hbuf[nb][kp * 512 + h] = v;                       // own slice, local
        stage[tid] = v;
        __syncwarp();

        // lanes 0-6: push this warp's 32-float block to one peer + release flag
        if (lane < 7) {
            const unsigned peer = (unsigned)lane + ((unsigned)lane >= (unsigned)rank ? 1u : 0u);
            const float4* sp = (const float4*)&stage[w * 32];
            const unsigned dstf = hb_a + ((unsigned)nb * 2048u + dblk) * 4u;
#pragma unroll
            for (int i = 0; i < 8; i++)
                dsmem_st_v4(dstf + (unsigned)i * 16u, peer, sp[i]);
            const unsigned fa = fl_a + (unsigned)(nb * 64 + rank * 8 + w) * 4u;
            dsmem_release_flag(fa, peer, (unsigned)(t + 1));
        }

        // global sequence output (not on the recurrence critical path)
        if (layer == 0)
            g_seq[((size_t)ta * B_ + b0 + kp) * 1024 + dir * 512 + h] = hcur;
        else
            out[((size_t)(b0 + kp) * T_ + ta) * 1024 + dir * 512 + h] = hcur;

        __syncthreads();   // own-slice + stage visibility for next step
    }

    // final hidden states
    hn[((size_t)c * B_ + b0 + kp) * H_ + h] = hprev;

    // no CTA may exit while peers can still push into its smem
    asm volatile("barrier.cluster.arrive.aligned;" ::: "memory");
    asm volatile("barrier.cluster.wait.aligned;"   ::: "memory");
}

// ---------------------------------------------------------------------------
extern "C" void kernel_launch(void* const* d_in, const int* in_sizes, int n_in,
                              void* d_out, int out_size) {
    const float* x        = (const float*)d_in[0];
    const float* mask     = (const float*)d_in[1];
    const float* w_ih     = (const float*)d_in[2];
    const float* w_hh     = (const float*)d_in[3];
    const float* b_ih     = (const float*)d_in[4];
    const float* b_hh     = (const float*)d_in[5];
    const float* noise_in = (const float*)d_in[6];
    const float* noise_h  = (const float*)d_in[7];
    float* out = (float*)d_out;                       // [B,T,2H]
    float* hn  = out + (size_t)B_ * T_ * 2 * H_;      // [L*D,B,H]

    dim3 gg(H_ / 64, TB_ / 128, 2);                   // (8, 256, 2)

    gemm_kernel<<<gg, 256>>>(x, w_ih, b_ih, b_hh, noise_in, 0);
    recur_kernel<<<128, 256>>>(w_hh, noise_h, mask, out, hn, 0);
    gemm_kernel<<<gg, 256>>>(x, w_ih, b_ih, b_hh, noise_in, 1);
    recur_kernel<<<128, 256>>>(w_hh, noise_h, mask, out, hn, 1);
}

// round 12
// speedup vs baseline: 1.2500x; 1.2500x over previous
#include <cuda_runtime.h>
#include <math.h>

#define T_   1024
#define B_   32
#define IN_  1024
#define H_   512
#define TB_  (T_ * B_)

typedef unsigned long long ull;

// ---------------- static device scratch (no runtime alloc allowed) ----------
__device__ float g_xin[2][(size_t)TB_ * H_];   // per-direction input projections (biases folded)
__device__ float g_seq[(size_t)TB_ * 2 * H_];  // layer-0 output, [t][b][2H]

// ---------------- f32x2 helpers (ptxas never emits FFMA2 from C++) ----------
__device__ __forceinline__ ull pk2(float lo, float hi) {
    ull r; asm("mov.b64 %0, {%1,%2};" : "=l"(r) : "f"(lo), "f"(hi)); return r;
}
__device__ __forceinline__ void upk2(ull v, float& lo, float& hi) {
    asm("mov.b64 {%0,%1}, %2;" : "=f"(lo), "=f"(hi) : "l"(v));
}
__device__ __forceinline__ void fma2(ull& d, ull a, ull b) {
    asm("fma.rn.f32x2 %0, %1, %2, %0;" : "+l"(d) : "l"(a), "l"(b));
}
__device__ __forceinline__ unsigned smem_u32(const void* p) {
    unsigned a;
    asm("{ .reg .u64 t; cvta.to.shared.u64 t, %1; cvt.u32.u64 %0, t; }" : "=r"(a) : "l"(p));
    return a;
}
// DSMEM push: map local smem addr to peer rank, scalar store
__device__ __forceinline__ void dsmem_st(unsigned laddr, unsigned rank, float v) {
    asm volatile(
        "{\n\t.reg .u32 ra;\n\t"
        "mapa.shared::cluster.u32 ra, %0, %1;\n\t"
        "st.shared::cluster.f32 [ra], %2;\n\t}"
        :: "r"(laddr), "r"(rank), "f"(v) : "memory");
}

// ---------------------------------------------------------------------------
// Input-projection GEMM (register-prefetch pipelined) — unchanged (proven).
// ---------------------------------------------------------------------------
__global__ __launch_bounds__(256, 2) void gemm_kernel(
    const float* __restrict__ x,
    const float* __restrict__ w_ih,
    const float* __restrict__ b_ih,
    const float* __restrict__ b_hh,
    const float* __restrict__ noise_in,
    int layer)
{
    __shared__ float As[16 * 132];   // [k][m], padded
    __shared__ float Bs[16 * 68];    // [k][n], padded

    const int tid  = threadIdx.x;
    const int cell = blockIdx.z;
    const int cabs = layer * 2 + cell;
    const int n0   = blockIdx.x * 64;
    const int m0   = blockIdx.y * 128;
    const int tx   = tid & 15;
    const int ty   = tid >> 4;
    const int msub = ty * 8;
    const int nsub = tx * 4;

    const float* A  = (layer == 0) ? x : g_seq;
    const float* nz = noise_in + (size_t)cabs * B_ * IN_;
    const float* wb = w_ih + (size_t)cabs * H_ * IN_;
    float* outp = g_xin[cell];

    ull acc[4][4];
#pragma unroll
    for (int i = 0; i < 4; i++)
#pragma unroll
        for (int j = 0; j < 4; j++) acc[i][j] = 0ull;

    const int e0 = tid, e1 = tid + 256;
    const int row0 = e0 >> 2, kq0 = (e0 & 3) * 4;
    const int row1 = e1 >> 2, kq1 = (e1 & 3) * 4;
    size_t ab0, ab1;
    if (layer == 0) {   // m = t*B + b ; x addr = b*(T*IN) + t*IN
        ab0 = (size_t)(row0 & 31) * ((size_t)T_ * IN_) + (size_t)(m0 / 32 + (row0 >> 5)) * IN_;
        ab1 = (size_t)(row1 & 31) * ((size_t)T_ * IN_) + (size_t)(m0 / 32 + (row1 >> 5)) * IN_;
    } else {
        ab0 = (size_t)(m0 + row0) * IN_;
        ab1 = (size_t)(m0 + row1) * IN_;
    }
    const size_t nb0 = (size_t)(row0 & 31) * IN_;
    const size_t nb1 = (size_t)(row1 & 31) * IN_;
    const int brow = tid >> 2, bkq = (tid & 3) * 4;
    const float* wrow = wb + (size_t)(n0 + brow) * IN_ + bkq;

    float4 xv0 = *(const float4*)(A + ab0 + kq0);
    float4 nv0 = *(const float4*)(nz + nb0 + kq0);
    float4 xv1 = *(const float4*)(A + ab1 + kq1);
    float4 nv1 = *(const float4*)(nz + nb1 + kq1);
    float4 wv0 = *(const float4*)(wrow);

    for (int k0 = 0; k0 < IN_; k0 += 16) {
        As[(kq0 + 0) * 132 + row0] = xv0.x * nv0.x;
        As[(kq0 + 1) * 132 + row0] = xv0.y * nv0.y;
        As[(kq0 + 2) * 132 + row0] = xv0.z * nv0.z;
        As[(kq0 + 3) * 132 + row0] = xv0.w * nv0.w;
        As[(kq1 + 0) * 132 + row1] = xv1.x * nv1.x;
        As[(kq1 + 1) * 132 + row1] = xv1.y * nv1.y;
        As[(kq1 + 2) * 132 + row1] = xv1.z * nv1.z;
        As[(kq1 + 3) * 132 + row1] = xv1.w * nv1.w;
        Bs[(bkq + 0) * 68 + brow] = wv0.x;
        Bs[(bkq + 1) * 68 + brow] = wv0.y;
        Bs[(bkq + 2) * 68 + brow] = wv0.z;
        Bs[(bkq + 3) * 68 + brow] = wv0.w;
        __syncthreads();

        const int kn = k0 + 16;
        if (kn < IN_) {
            xv0 = *(const float4*)(A + ab0 + kn + kq0);
            nv0 = *(const float4*)(nz + nb0 + kn + kq0);
            xv1 = *(const float4*)(A + ab1 + kn + kq1);
            nv1 = *(const float4*)(nz + nb1 + kn + kq1);
            wv0 = *(const float4*)(wrow + kn);
        }

#pragma unroll
        for (int k = 0; k < 16; k++) {
            float4 b4 = *(const float4*)&Bs[k * 68 + nsub];
            ull bd0 = pk2(b4.x, b4.x);
            ull bd1 = pk2(b4.y, b4.y);
            ull bd2 = pk2(b4.z, b4.z);
            ull bd3 = pk2(b4.w, b4.w);
#pragma unroll
            for (int mp = 0; mp < 4; mp++) {
                ull au = *(const ull*)&As[k * 132 + msub + 2 * mp];
                fma2(acc[mp][0], au, bd0);
                fma2(acc[mp][1], au, bd1);
                fma2(acc[mp][2], au, bd2);
                fma2(acc[mp][3], au, bd3);
            }
        }
        __syncthreads();
    }

    float bi[4];
#pragma unroll
    for (int nn = 0; nn < 4; nn++) {
        int n = n0 + nsub + nn;
        bi[nn] = b_ih[cabs * H_ + n] + b_hh[cabs * H_ + n];
    }
#pragma unroll
    for (int mp = 0; mp < 4; mp++) {
        float lo[4], hi[4];
#pragma unroll
        for (int nn = 0; nn < 4; nn++) upk2(acc[mp][nn], lo[nn], hi[nn]);
        float4 v0 = make_float4(lo[0] + bi[0], lo[1] + bi[1], lo[2] + bi[2], lo[3] + bi[3]);
        float4 v1 = make_float4(hi[0] + bi[0], hi[1] + bi[1], hi[2] + bi[2], hi[3] + bi[3]);
        size_t r0 = (size_t)(m0 + msub + 2 * mp) * H_ + n0 + nsub;
        *(float4*)(outp + r0)      = v0;
        *(float4*)(outp + r0 + H_) = v1;
    }
}

// ---------------------------------------------------------------------------
// Recurrent scan v6: R9's proven sync structure (one combined cluster
// arrive+wait per step) with 512 threads/CTA and K-split 8 for latency
// hiding (4 warps/SMSP instead of 2). 16 clusters of 8 CTAs; CTA owns
// 4 batches x 64 h-cols; W_hh slice register-resident as f32x2 pairs.
// Next-step xin/mask prefetch is issued in the epilogue so its L2 refill
// (L1 is flushed by cluster.sync) overlaps the sync + next FMA phase.
// ---------------------------------------------------------------------------
__global__ __launch_bounds__(512, 1) __cluster_dims__(8, 1, 1)
void recur_kernel(
    const float* __restrict__ w_hh,
    const float* __restrict__ noise_h,
    const float* __restrict__ mask,
    float* __restrict__ out,      // d_out: [B,T,2H] (layer 1 writes here)
    float* __restrict__ hn,       // d_out + B*T*2H: [L*D,B,H]
    int layer)
{
    __shared__ float hbuf[2][4 * 512];        // full h*nh vector, double buffered (16KB)
    __shared__ float red2[8][4][64];          // [kp][b][hl] split-K partials (8KB)

    const int tid  = threadIdx.x;
    const int bx   = blockIdx.x;
    const int dir  = bx >> 6;                 // 0 fwd, 1 bwd
    const int rank = bx & 7;                  // cluster rank == h-slice
    const int grp  = (bx >> 3) & 7;           // batch group
    const int b0   = grp * 4;
    const int h0   = rank * 64;
    const int kp   = tid >> 6;                // K partition (0..7)
    const int hl   = tid & 63;
    const int h    = h0 + hl;
    const int c    = layer * 2 + dir;

    const unsigned hb_a = smem_u32(&hbuf[0][0]);

    // W_hh slice in registers: w[h][kp*64 .. +64) as 16 aligned f32x2 pairs
    union F4U2 { float4 f; ulonglong2 u; };
    ulonglong2 wu[16];
    {
        const float4* wp = (const float4*)(w_hh + ((size_t)c * H_ + h) * H_ + kp * 64);
#pragma unroll
        for (int i = 0; i < 16; i++) { F4U2 t; t.f = wp[i]; wu[i] = t.u; }
    }

    // epilogue threads: kp<4 own output (b=kp, h)
    const bool epi = (kp < 4);
    float nh = 0.0f, hprev = 0.0f;
    float xv = 0.0f, mt = 0.0f;
    const float* xin = g_xin[dir];
    if (epi) {
        nh = noise_h[((size_t)c * B_ + b0 + kp) * H_ + h];
        const int ta0 = dir ? (T_ - 1) : 0;
        xv = __ldg(xin + ((size_t)ta0 * B_ + b0 + kp) * H_ + h);
        mt = __ldg(mask + (size_t)(b0 + kp) * T_ + ta0);
    }
    const unsigned my_off = (unsigned)(kp * 512 + h) * 4u;  // valid when epi

    for (int t = 0; t < T_; t++) {
        const int ta = dir ? (T_ - 1 - t) : t;

        // dot products over our K slice (local hbuf, broadcast LDS.128)
        ull acc[4] = {0ull, 0ull, 0ull, 0ull};
        if (t > 0) {
            const float4* hb = (const float4*)&hbuf[t & 1][0];
#pragma unroll
            for (int i = 0; i < 16; i++) {
                ulonglong2 w2 = wu[i];
#pragma unroll
                for (int b = 0; b < 4; b++) {
                    F4U2 q; q.f = hb[b * 128 + kp * 16 + i];
                    fma2(acc[b], q.u.x, w2.x);
                    fma2(acc[b], q.u.y, w2.y);
                }
            }
        }
#pragma unroll
        for (int b = 0; b < 4; b++) {
            float lo, hi; upk2(acc[b], lo, hi);
            red2[kp][b][hl] = lo + hi;
        }
        __syncthreads();

        // epilogue: thread (kp<4, hl) finishes output (b=kp, h)
        if (epi) {
            float rec = 0.0f;
#pragma unroll
            for (int q = 0; q < 8; q++) rec += red2[q][kp][hl];
            const float hnew = tanhf(xv + rec);           // biases folded in xin
            const float hcur = hnew * mt + hprev * (1.0f - mt);
            hprev = hcur;
            const float v = hcur * nh;
            const int nb = (t + 1) & 1;
            hbuf[nb][kp * 512 + h] = v;                   // own slice, local
            const unsigned dst = hb_a + (unsigned)(nb * 8192) + my_off;
#pragma unroll
            for (unsigned r = 0; r < 8; r++)
                if (r != (unsigned)rank) dsmem_st(dst, r, v);
            if (layer == 0)
                g_seq[((size_t)ta * B_ + b0 + kp) * 1024 + dir * 512 + h] = hcur;
            else
                out[((size_t)(b0 + kp) * T_ + ta) * 1024 + dir * 512 + h] = hcur;

            // prefetch next step's xin/mask: in flight across the sync
            if (t + 1 < T_) {
                const int tn = dir ? (T_ - 2 - t) : (t + 1);
                xv = __ldg(xin + ((size_t)tn * B_ + b0 + kp) * H_ + h);
                mt = __ldg(mask + (size_t)(b0 + kp) * T_ + tn);
            }
        }

        // combined cluster barrier (R9-proven): releases the pushes,
        // gates every CTA's next step. One-step producer lead impossible.
        asm volatile("barrier.cluster.arrive.aligned;" ::: "memory");
        asm volatile("barrier.cluster.wait.aligned;"   ::: "memory");
    }

    // after final barrier no peer can push into our smem
    if (epi)
        hn[((size_t)c * B_ + b0 + kp) * H_ + h] = hprev;
}

// ---------------------------------------------------------------------------
extern "C" void kernel_launch(void* const* d_in, const int* in_sizes, int n_in,
                              void* d_out, int out_size) {
    const float* x        = (const float*)d_in[0];
    const float* mask     = (const float*)d_in[1];
    const float* w_ih     = (const float*)d_in[2];
    const float* w_hh     = (const float*)d_in[3];
    const float* b_ih     = (const float*)d_in[4];
    const float* b_hh     = (const float*)d_in[5];
    const float* noise_in = (const float*)d_in[6];
    const float* noise_h  = (const float*)d_in[7];
    float* out = (float*)d_out;                       // [B,T,2H]
    float* hn  = out + (size_t)B_ * T_ * 2 * H_;      // [L*D,B,H]

    dim3 gg(H_ / 64, TB_ / 128, 2);                   // (8, 256, 2)

    gemm_kernel<<<gg, 256>>>(x, w_ih, b_ih, b_hh, noise_in, 0);
    recur_kernel<<<128, 512>>>(w_hh, noise_h, mask, out, hn, 0);
    gemm_kernel<<<gg, 256>>>(x, w_ih, b_ih, b_hh, noise_in, 1);
    recur_kernel<<<128, 512>>>(w_hh, noise_h, mask, out, hn, 1);
}